// round 1
// baseline (speedup 1.0000x reference)
#include <cuda_runtime.h>
#include <math.h>

#define N_FFT 512
#define HOP 128
#define NBINS 257            // n_fft/2 + 1
#define MAX_FRAMES 32769     // 2^22 / 128 + 1
#define TWO_PI_F 6.28318530717958647692f

// diff field d[t][f] = pr - pg, layout [T', NBINS] row-major (f contiguous)
__device__ float g_diff[(size_t)MAX_FRAMES * NBINS];
__device__ double g_acc[3];

__global__ void zero_acc_kernel() {
    g_acc[0] = 0.0; g_acc[1] = 0.0; g_acc[2] = 0.0;
}

__device__ __forceinline__ int reflect_idx(int j, int T) {
    // jnp.pad(..., mode='reflect'): edge excluded; single reflection suffices
    j = abs(j);
    if (j >= T) j = 2 * T - 2 - j;
    return j;
}

// One CTA per frame: packed complex FFT (yd -> re, td -> im), 9 radix-2 stages,
// spectral split + atan2 phases, store pr - pg.
__global__ __launch_bounds__(256) void fft_phase_kernel(
    const float* __restrict__ yd, const float* __restrict__ td,
    int T, int n_frames)
{
    __shared__ float2 z[N_FFT];
    __shared__ float2 tw[N_FFT / 2];

    const int frame = blockIdx.x;
    const int tid = threadIdx.x;   // 0..255

    // twiddles: tw[k] = exp(-2*pi*i*k/512), exact-argument sincospi
    {
        float s, c;
        sincospif(-(float)tid * (1.0f / 256.0f), &s, &c);
        tw[tid] = make_float2(c, s);
    }

    // load frame with reflect padding, bit-reversed placement
    const int base = frame * HOP - (N_FFT / 2);
#pragma unroll
    for (int e = tid; e < N_FFT; e += 256) {
        int src = reflect_idx(base + e, T);
        int r = __brev((unsigned)e) >> 23;   // 9-bit reverse
        z[r] = make_float2(yd[src], td[src]);
    }
    __syncthreads();

    // 9 DIT radix-2 stages
#pragma unroll
    for (int s = 1; s <= 9; s++) {
        const int half = 1 << (s - 1);
        const int k = tid & (half - 1);
        const int i0 = ((tid >> (s - 1)) << s) | k;
        const int i1 = i0 + half;
        float2 w = tw[k << (9 - s)];
        float2 a = z[i0];
        float2 b = z[i1];
        float tr = w.x * b.x - w.y * b.y;
        float ti = w.x * b.y + w.y * b.x;
        z[i0] = make_float2(a.x + tr, a.y + ti);
        z[i1] = make_float2(a.x - tr, a.y - ti);
        __syncthreads();
    }

    // split packed spectrum; constant factors of 1/2 don't affect angle
    for (int f = tid; f < NBINS; f += 256) {
        float2 Zk = z[f];
        float2 Zn = z[(N_FFT - f) & (N_FFT - 1)];
        // Yd[f] = (Z[f] + conj(Z[N-f]))/2
        float yre = Zk.x + Zn.x;
        float yim = Zk.y - Zn.y;
        // Td[f] = (Z[f] - conj(Z[N-f]))/(2i)  ->  re=(Zk.y+Zn.y), im=(Zn.x-Zk.x)
        float tre = Zk.y + Zn.y;
        float tim = Zn.x - Zk.x;
        float pr = atan2f(yim, yre);
        float pg = atan2f(tim, tre);
        g_diff[(size_t)frame * NBINS + f] = pr - pg;
    }
}

__device__ __forceinline__ float anti_wrap(float x) {
    // |x - round(x/2pi)*2pi|; rintf = round-half-to-even matches jnp.round
    return fabsf(fmaf(-rintf(x * (1.0f / TWO_PI_F)), TWO_PI_F, x));
}

__global__ __launch_bounds__(256) void reduce_kernel(int n_frames) {
    const size_t total = (size_t)n_frames * NBINS;
    float s_ip = 0.0f, s_gd = 0.0f, s_iaf = 0.0f;

    for (size_t n = (size_t)blockIdx.x * blockDim.x + threadIdx.x;
         n < total;
         n += (size_t)gridDim.x * blockDim.x)
    {
        const int f = (int)(n % NBINS);
        const float d0 = g_diff[n];

        s_ip += anti_wrap(d0);

        // gd along f: f==0 -> aw(-d0) == aw(d0)
        float gdv = (f == 0) ? d0 : (g_diff[n - 1] - d0);
        s_gd += anti_wrap(gdv);

        // iaf along t: t==0 (n < NBINS) -> aw(-d0) == aw(d0)
        float iafv = (n < (size_t)NBINS) ? d0 : (g_diff[n - NBINS] - d0);
        s_iaf += anti_wrap(iafv);
    }

    // warp reduce
#pragma unroll
    for (int o = 16; o > 0; o >>= 1) {
        s_ip  += __shfl_down_sync(0xFFFFFFFFu, s_ip,  o);
        s_gd  += __shfl_down_sync(0xFFFFFFFFu, s_gd,  o);
        s_iaf += __shfl_down_sync(0xFFFFFFFFu, s_iaf, o);
    }
    if ((threadIdx.x & 31) == 0) {
        atomicAdd(&g_acc[0], (double)s_ip);
        atomicAdd(&g_acc[1], (double)s_gd);
        atomicAdd(&g_acc[2], (double)s_iaf);
    }
}

__global__ void finalize_kernel(float* __restrict__ out, int n_frames) {
    const double cnt = (double)n_frames * (double)NBINS;
    if (threadIdx.x < 3) {
        out[threadIdx.x] = (float)(g_acc[threadIdx.x] / cnt);
    }
}

extern "C" void kernel_launch(void* const* d_in, const int* in_sizes, int n_in,
                              void* d_out, int out_size) {
    const float* yd = (const float*)d_in[0];
    const float* td = (const float*)d_in[1];
    const int T = in_sizes[0];

    // n_frames = ((T + 2*pad) - n_fft)/hop + 1 with pad = n_fft/2
    int n_frames = T / HOP + 1;
    if (n_frames > MAX_FRAMES) n_frames = MAX_FRAMES;

    zero_acc_kernel<<<1, 1>>>();
    fft_phase_kernel<<<n_frames, 256>>>(yd, td, T, n_frames);
    reduce_kernel<<<1184, 256>>>(n_frames);
    finalize_kernel<<<1, 32>>>((float*)d_out, n_frames);
}

// round 2
// speedup vs baseline: 2.4051x; 2.4051x over previous
#include <cuda_runtime.h>
#include <math.h>

#define N_FFT 512
#define HOP 128
#define NBINS 257
#define MAX_FRAMES 32769
#define TWO_PI_F 6.28318530717958647692f

__device__ float g_diff[(size_t)MAX_FRAMES * NBINS];
__device__ double g_acc[3];

__global__ void zero_acc_kernel() {
    g_acc[0] = 0.0; g_acc[1] = 0.0; g_acc[2] = 0.0;
}

__device__ __forceinline__ int reflect_idx(int j, int T) {
    j = abs(j);
    if (j >= T) j = 2 * T - 2 - j;
    return j;
}

// In-register 8-point DFT (DIF internally, outputs written in NATURAL order).
// X[v] = sum_k x[k] * exp(-2*pi*i*k*v/8)
__device__ __forceinline__ void dft8(float xr[8], float xi[8]) {
    const float C = 0.70710678118654752440f;
    float sr[4], si[4], tr[4], ti[4];
#pragma unroll
    for (int n = 0; n < 4; n++) {
        sr[n] = xr[n] + xr[n + 4];
        si[n] = xi[n] + xi[n + 4];
    }
    float ur, ui;
    ur = xr[0] - xr[4]; ui = xi[0] - xi[4];
    tr[0] = ur;              ti[0] = ui;
    ur = xr[1] - xr[5]; ui = xi[1] - xi[5];
    tr[1] = C * (ur + ui);   ti[1] = C * (ui - ur);      // * W8^1
    ur = xr[2] - xr[6]; ui = xi[2] - xi[6];
    tr[2] = ui;              ti[2] = -ur;                // * -i
    ur = xr[3] - xr[7]; ui = xi[3] - xi[7];
    tr[3] = C * (ui - ur);   ti[3] = -C * (ur + ui);     // * W8^3

    // even outputs from s (4-pt DIF)
    float e0r = sr[0] + sr[2], e0i = si[0] + si[2];
    float e2r = sr[0] - sr[2], e2i = si[0] - si[2];
    float e1r = sr[1] + sr[3], e1i = si[1] + si[3];
    float e3r = si[1] - si[3], e3i = sr[3] - sr[1];      // (s1-s3)*(-i)
    xr[0] = e0r + e1r; xi[0] = e0i + e1i;
    xr[4] = e0r - e1r; xi[4] = e0i - e1i;
    xr[2] = e2r + e3r; xi[2] = e2i + e3i;
    xr[6] = e2r - e3r; xi[6] = e2i - e3i;
    // odd outputs from t
    float g0r = tr[0] + tr[2], g0i = ti[0] + ti[2];
    float g2r = tr[0] - tr[2], g2i = ti[0] - ti[2];
    float g1r = tr[1] + tr[3], g1i = ti[1] + ti[3];
    float g3r = ti[1] - ti[3], g3i = tr[3] - tr[1];
    xr[1] = g0r + g1r; xi[1] = g0i + g1i;
    xr[5] = g0r - g1r; xi[5] = g0i - g1i;
    xr[3] = g2r + g3r; xi[3] = g2i + g3i;
    xr[7] = g2r - g3r; xi[7] = g2i - g3i;
}

// 4 frames per 256-thread CTA; 64 threads per frame; radix-8^3 register FFT.
// n = 64k + t. Stage A: dft8 over k -> z[v]; * W512^{t v}.
// Stage B: over t2 (t = t1 + 8 t2): dft8 -> m1; * W64^{t1 m1}.
// Stage C: over t1: dft8 -> m2.  X[64 m2 + 8 m1 + v].
__global__ __launch_bounds__(256) void fft_phase_kernel(
    const float* __restrict__ yd, const float* __restrict__ td,
    int T, int n_frames)
{
    __shared__ float sRe[4][576];
    __shared__ float sIm[4][576];

    const int lt = threadIdx.x & 63;   // thread within frame
    const int fl = threadIdx.x >> 6;   // frame slot in CTA
    const int frame = blockIdx.x * 4 + fl;
    const bool active = (frame < n_frames);

    float xr[8], xi[8];

    // ---- load with reflect padding: reg k = x[64k + lt] ----
    if (active) {
        const int base = frame * HOP - (N_FFT / 2) + lt;
#pragma unroll
        for (int k = 0; k < 8; k++) {
            int j = reflect_idx(base + 64 * k, T);
            xr[k] = yd[j];
            xi[k] = td[j];
        }
    } else {
#pragma unroll
        for (int k = 0; k < 8; k++) { xr[k] = 0.0f; xi[k] = 0.0f; }
    }

    // ---- Stage A ----
    dft8(xr, xi);
    {
        float bs, bc;
        sincospif(-(float)lt * (1.0f / 256.0f), &bs, &bc);  // W512^lt
        float wr = bc, wi = bs;
#pragma unroll
        for (int v = 1; v < 8; v++) {
            float nr = xr[v] * wr - xi[v] * wi;
            float ni = xr[v] * wi + xi[v] * wr;
            xr[v] = nr; xi[v] = ni;
            float t2r = wr * bc - wi * bs;
            float t2i = wr * bs + wi * bc;
            wr = t2r; wi = t2i;
        }
    }
    // transpose: S[v*72 + t]
#pragma unroll
    for (int v = 0; v < 8; v++) {
        sRe[fl][v * 72 + lt] = xr[v];
        sIm[fl][v * 72 + lt] = xi[v];
    }
    __syncthreads();

    // ---- Stage B ----
    const int v2 = lt >> 3;
    const int t1 = lt & 7;
#pragma unroll
    for (int t2 = 0; t2 < 8; t2++) {
        int a = v2 * 72 + t1 + 8 * t2;
        xr[t2] = sRe[fl][a];
        xi[t2] = sIm[fl][a];
    }
    dft8(xr, xi);   // -> index m1
    {
        float bs, bc;
        sincospif(-(float)t1 * (1.0f / 32.0f), &bs, &bc);   // W64^t1
        float wr = bc, wi = bs;
#pragma unroll
        for (int m1 = 1; m1 < 8; m1++) {
            float nr = xr[m1] * wr - xi[m1] * wi;
            float ni = xr[m1] * wi + xi[m1] * wr;
            xr[m1] = nr; xi[m1] = ni;
            float t2r = wr * bc - wi * bs;
            float t2i = wr * bs + wi * bc;
            wr = t2r; wi = t2i;
        }
    }
    __syncthreads();   // smem buffer reuse barrier
    // transpose: T[(v2*8 + m1)*9 + t1]
#pragma unroll
    for (int m1 = 0; m1 < 8; m1++) {
        int a = (v2 * 8 + m1) * 9 + t1;
        sRe[fl][a] = xr[m1];
        sIm[fl][a] = xi[m1];
    }
    __syncthreads();

    // ---- Stage C ----  thread <-> row (v, m1) = lt
    {
        const int rowbase = lt * 9;
#pragma unroll
        for (int k = 0; k < 8; k++) {
            xr[k] = sRe[fl][rowbase + k];
            xi[k] = sIm[fl][rowbase + k];
        }
    }
    dft8(xr, xi);   // -> index m2
    __syncthreads();
    {
        const int fbase = ((lt & 7) << 3) | (lt >> 3);  // 8*m1 + v
#pragma unroll
        for (int m2 = 0; m2 < 8; m2++) {
            sRe[fl][64 * m2 + fbase] = xr[m2];
            sIm[fl][64 * m2 + fbase] = xi[m2];
        }
    }
    __syncthreads();

    // ---- epilogue: split packed spectrum, phases, diff ----
    if (active) {
        const size_t obase = (size_t)frame * NBINS;
#pragma unroll
        for (int j = 0; j < 5; j++) {
            int f = lt + 64 * j;
            if (f <= 256) {
                float zkr = sRe[fl][f];
                float zki = sIm[fl][f];
                int m = (N_FFT - f) & (N_FFT - 1);
                float znr = sRe[fl][m];
                float zni = sIm[fl][m];
                float yre = zkr + znr;
                float yim = zki - zni;
                float tre = zki + zni;
                float tim = znr - zkr;
                float pr = atan2f(yim, yre);
                float pg = atan2f(tim, tre);
                g_diff[obase + f] = pr - pg;
            }
        }
    }
}

__device__ __forceinline__ float anti_wrap(float x) {
    return fabsf(fmaf(-rintf(x * (1.0f / TWO_PI_F)), TWO_PI_F, x));
}

__global__ __launch_bounds__(256) void reduce_kernel(int n_frames) {
    const int tid = threadIdx.x;
    float s_ip = 0.0f, s_gd = 0.0f, s_iaf = 0.0f;

    for (int t = blockIdx.x; t < n_frames; t += gridDim.x) {
        const size_t base = (size_t)t * NBINS;
        {
            float d0 = g_diff[base + tid];
            s_ip += anti_wrap(d0);
            float gdv = (tid == 0) ? d0 : (g_diff[base + tid - 1] - d0);
            s_gd += anti_wrap(gdv);
            float iafv = (t == 0) ? d0 : (g_diff[base - NBINS + tid] - d0);
            s_iaf += anti_wrap(iafv);
        }
        if (tid == 0) {
            float d0 = g_diff[base + 256];
            s_ip += anti_wrap(d0);
            s_gd += anti_wrap(g_diff[base + 255] - d0);
            float iafv = (t == 0) ? d0 : (g_diff[base - NBINS + 256] - d0);
            s_iaf += anti_wrap(iafv);
        }
    }

#pragma unroll
    for (int o = 16; o > 0; o >>= 1) {
        s_ip  += __shfl_down_sync(0xFFFFFFFFu, s_ip,  o);
        s_gd  += __shfl_down_sync(0xFFFFFFFFu, s_gd,  o);
        s_iaf += __shfl_down_sync(0xFFFFFFFFu, s_iaf, o);
    }
    if ((tid & 31) == 0) {
        atomicAdd(&g_acc[0], (double)s_ip);
        atomicAdd(&g_acc[1], (double)s_gd);
        atomicAdd(&g_acc[2], (double)s_iaf);
    }
}

__global__ void finalize_kernel(float* __restrict__ out, int n_frames) {
    const double cnt = (double)n_frames * (double)NBINS;
    if (threadIdx.x < 3) {
        out[threadIdx.x] = (float)(g_acc[threadIdx.x] / cnt);
    }
}

extern "C" void kernel_launch(void* const* d_in, const int* in_sizes, int n_in,
                              void* d_out, int out_size) {
    const float* yd = (const float*)d_in[0];
    const float* td = (const float*)d_in[1];
    const int T = in_sizes[0];

    int n_frames = T / HOP + 1;
    if (n_frames > MAX_FRAMES) n_frames = MAX_FRAMES;

    zero_acc_kernel<<<1, 1>>>();
    fft_phase_kernel<<<(n_frames + 3) / 4, 256>>>(yd, td, T, n_frames);
    reduce_kernel<<<1184, 256>>>(n_frames);
    finalize_kernel<<<1, 32>>>((float*)d_out, n_frames);
}

// round 3
// speedup vs baseline: 3.2377x; 1.3462x over previous
#include <cuda_runtime.h>
#include <math.h>

#define N_FFT 512
#define HOP 128
#define NBINS 257
#define MAX_FRAMES 32769
#define MAX_CTAS ((MAX_FRAMES + 3) / 4)
#define TWO_PI_F 6.28318530717958647692f

__device__ float g_first[(size_t)MAX_CTAS * NBINS];  // d row of each CTA's first frame
__device__ float g_last[(size_t)MAX_CTAS * NBINS];   // d row of each CTA's last (4th) frame
__device__ double g_acc[3];                           // zero-init at load; self-cleaned
__device__ unsigned int g_done;                       // ticket counter; self-cleaned

__device__ __forceinline__ int reflect_idx(int j, int T) {
    j = abs(j);
    if (j >= T) j = 2 * T - 2 - j;
    return j;
}

__device__ __forceinline__ float anti_wrap(float x) {
    return fabsf(fmaf(-rintf(x * (1.0f / TWO_PI_F)), TWO_PI_F, x));
}

// In-register 8-point DFT, outputs in natural order.
__device__ __forceinline__ void dft8(float xr[8], float xi[8]) {
    const float C = 0.70710678118654752440f;
    float sr[4], si[4], tr[4], ti[4];
#pragma unroll
    for (int n = 0; n < 4; n++) {
        sr[n] = xr[n] + xr[n + 4];
        si[n] = xi[n] + xi[n + 4];
    }
    float ur, ui;
    ur = xr[0] - xr[4]; ui = xi[0] - xi[4];
    tr[0] = ur;              ti[0] = ui;
    ur = xr[1] - xr[5]; ui = xi[1] - xi[5];
    tr[1] = C * (ur + ui);   ti[1] = C * (ui - ur);
    ur = xr[2] - xr[6]; ui = xi[2] - xi[6];
    tr[2] = ui;              ti[2] = -ur;
    ur = xr[3] - xr[7]; ui = xi[3] - xi[7];
    tr[3] = C * (ui - ur);   ti[3] = -C * (ur + ui);

    float e0r = sr[0] + sr[2], e0i = si[0] + si[2];
    float e2r = sr[0] - sr[2], e2i = si[0] - si[2];
    float e1r = sr[1] + sr[3], e1i = si[1] + si[3];
    float e3r = si[1] - si[3], e3i = sr[3] - sr[1];
    xr[0] = e0r + e1r; xi[0] = e0i + e1i;
    xr[4] = e0r - e1r; xi[4] = e0i - e1i;
    xr[2] = e2r + e3r; xi[2] = e2i + e3i;
    xr[6] = e2r - e3r; xi[6] = e2i - e3i;
    float g0r = tr[0] + tr[2], g0i = ti[0] + ti[2];
    float g2r = tr[0] - tr[2], g2i = ti[0] - ti[2];
    float g1r = tr[1] + tr[3], g1i = ti[1] + ti[3];
    float g3r = ti[1] - ti[3], g3i = tr[3] - tr[1];
    xr[1] = g0r + g1r; xi[1] = g0i + g1i;
    xr[5] = g0r - g1r; xi[5] = g0i - g1i;
    xr[3] = g2r + g3r; xi[3] = g2i + g3i;
    xr[7] = g2r - g3r; xi[7] = g2i - g3i;
}

// 4 frames per 256-thread CTA; radix-8^3 register FFT; fused loss partial sums.
__global__ __launch_bounds__(256) void fft_phase_kernel(
    const float* __restrict__ yd, const float* __restrict__ td,
    int T, int n_frames)
{
    __shared__ float sRe[4][576];
    __shared__ float sIm[4][576];
    __shared__ float dBuf[4][260];
    __shared__ float wsum[8][3];

    const int lt = threadIdx.x & 63;
    const int fl = threadIdx.x >> 6;
    const int frame = blockIdx.x * 4 + fl;
    const bool active = (frame < n_frames);

    float xr[8], xi[8];

    if (active) {
        const int base = frame * HOP - (N_FFT / 2) + lt;
#pragma unroll
        for (int k = 0; k < 8; k++) {
            int j = reflect_idx(base + 64 * k, T);
            xr[k] = yd[j];
            xi[k] = td[j];
        }
    } else {
#pragma unroll
        for (int k = 0; k < 8; k++) { xr[k] = 0.0f; xi[k] = 0.0f; }
    }

    // ---- Stage A: dft8 over k, twiddle W512^{lt*v} ----
    dft8(xr, xi);
    {
        float bs, bc;
        sincospif(-(float)lt * (1.0f / 256.0f), &bs, &bc);
        float wr = bc, wi = bs;
#pragma unroll
        for (int v = 1; v < 8; v++) {
            float nr = xr[v] * wr - xi[v] * wi;
            float ni = xr[v] * wi + xi[v] * wr;
            xr[v] = nr; xi[v] = ni;
            float t2r = wr * bc - wi * bs;
            float t2i = wr * bs + wi * bc;
            wr = t2r; wi = t2i;
        }
    }
#pragma unroll
    for (int v = 0; v < 8; v++) {
        sRe[fl][v * 72 + lt] = xr[v];
        sIm[fl][v * 72 + lt] = xi[v];
    }
    __syncthreads();

    // ---- Stage B: dft8 over t2, twiddle W64^{t1*m1} ----
    const int v2 = lt >> 3;
    const int t1 = lt & 7;
#pragma unroll
    for (int t2 = 0; t2 < 8; t2++) {
        int a = v2 * 72 + t1 + 8 * t2;
        xr[t2] = sRe[fl][a];
        xi[t2] = sIm[fl][a];
    }
    dft8(xr, xi);
    {
        float bs, bc;
        sincospif(-(float)t1 * (1.0f / 32.0f), &bs, &bc);
        float wr = bc, wi = bs;
#pragma unroll
        for (int m1 = 1; m1 < 8; m1++) {
            float nr = xr[m1] * wr - xi[m1] * wi;
            float ni = xr[m1] * wi + xi[m1] * wr;
            xr[m1] = nr; xi[m1] = ni;
            float t2r = wr * bc - wi * bs;
            float t2i = wr * bs + wi * bc;
            wr = t2r; wi = t2i;
        }
    }
    __syncthreads();
#pragma unroll
    for (int m1 = 0; m1 < 8; m1++) {
        int a = (v2 * 8 + m1) * 9 + t1;
        sRe[fl][a] = xr[m1];
        sIm[fl][a] = xi[m1];
    }
    __syncthreads();

    // ---- Stage C ----
    {
        const int rowbase = lt * 9;
#pragma unroll
        for (int k = 0; k < 8; k++) {
            xr[k] = sRe[fl][rowbase + k];
            xi[k] = sIm[fl][rowbase + k];
        }
    }
    dft8(xr, xi);
    __syncthreads();
    {
        const int fbase = ((lt & 7) << 3) | (lt >> 3);
#pragma unroll
        for (int m2 = 0; m2 < 8; m2++) {
            sRe[fl][64 * m2 + fbase] = xr[m2];
            sIm[fl][64 * m2 + fbase] = xi[m2];
        }
    }
    __syncthreads();

    // ---- epilogue: split spectrum, d = angle(Y * conj(T)) in ONE atan2 ----
    if (active) {
        const size_t obase = (size_t)blockIdx.x * NBINS;
#pragma unroll
        for (int j = 0; j < 5; j++) {
            int f = lt + 64 * j;
            if (f <= 256) {
                float zkr = sRe[fl][f];
                float zki = sIm[fl][f];
                int m = (N_FFT - f) & (N_FFT - 1);
                float znr = sRe[fl][m];
                float zni = sIm[fl][m];
                float yre = zkr + znr;
                float yim = zki - zni;
                float tre = zki + zni;
                float tim = znr - zkr;
                // P = Y * conj(T)
                float pre = yre * tre + yim * tim;
                float pim = yim * tre - yre * tim;
                float d = atan2f(pim, pre);
                dBuf[fl][f] = d;
                if (fl == 0) g_first[obase + f] = d;
                if (fl == 3) g_last[obase + f] = d;
            }
        }
    }
    __syncthreads();

    // ---- fused partial sums: ip, gd (all intra-frame), iaf (intra-CTA pairs) ----
    float s_ip = 0.0f, s_gd = 0.0f, s_iaf = 0.0f;
    const int tid = threadIdx.x;
    for (int idx = tid; idx < 4 * NBINS; idx += 256) {
        int fl2 = idx / NBINS;
        int f = idx - fl2 * NBINS;
        int fr2 = blockIdx.x * 4 + fl2;
        if (fr2 < n_frames) {
            float d0 = dBuf[fl2][f];
            s_ip += anti_wrap(d0);
            float gdv = (f == 0) ? d0 : (dBuf[fl2][f - 1] - d0);
            s_gd += anti_wrap(gdv);
            if (fl2 > 0) s_iaf += anti_wrap(dBuf[fl2 - 1][f] - d0);
        }
    }
#pragma unroll
    for (int o = 16; o > 0; o >>= 1) {
        s_ip  += __shfl_down_sync(0xFFFFFFFFu, s_ip,  o);
        s_gd  += __shfl_down_sync(0xFFFFFFFFu, s_gd,  o);
        s_iaf += __shfl_down_sync(0xFFFFFFFFu, s_iaf, o);
    }
    if ((tid & 31) == 0) {
        wsum[tid >> 5][0] = s_ip;
        wsum[tid >> 5][1] = s_gd;
        wsum[tid >> 5][2] = s_iaf;
    }
    __syncthreads();
    if (tid == 0) {
        double a0 = 0.0, a1 = 0.0, a2 = 0.0;
#pragma unroll
        for (int w = 0; w < 8; w++) {
            a0 += (double)wsum[w][0];
            a1 += (double)wsum[w][1];
            a2 += (double)wsum[w][2];
        }
        atomicAdd(&g_acc[0], a0);
        atomicAdd(&g_acc[1], a1);
        atomicAdd(&g_acc[2], a2);
    }
}

// Boundary iaf terms (t = 4b for b>=1, plus t=0 row) + finalize via ticket.
__global__ __launch_bounds__(256) void boundary_finalize_kernel(
    float* __restrict__ out, int n_frames, int n_cta)
{
    __shared__ float wsum[8];
    const size_t total = (size_t)n_cta * NBINS;
    float s_iaf = 0.0f;

    for (size_t n = (size_t)blockIdx.x * blockDim.x + threadIdx.x;
         n < total;
         n += (size_t)gridDim.x * blockDim.x)
    {
        int b = (int)(n / NBINS);
        float dv = g_first[n];
        float term = (b == 0) ? dv : (g_last[n - NBINS] - dv);
        s_iaf += anti_wrap(term);
    }

#pragma unroll
    for (int o = 16; o > 0; o >>= 1)
        s_iaf += __shfl_down_sync(0xFFFFFFFFu, s_iaf, o);
    if ((threadIdx.x & 31) == 0) wsum[threadIdx.x >> 5] = s_iaf;
    __syncthreads();

    if (threadIdx.x == 0) {
        double a = 0.0;
#pragma unroll
        for (int w = 0; w < 8; w++) a += (double)wsum[w];
        atomicAdd(&g_acc[2], a);
        __threadfence();
        unsigned int ticket = atomicAdd(&g_done, 1u);
        if (ticket == gridDim.x - 1) {
            // last block: all g_acc updates visible
            double cnt = (double)n_frames * (double)NBINS;
            volatile double* acc = g_acc;
            out[0] = (float)(acc[0] / cnt);
            out[1] = (float)(acc[1] / cnt);
            out[2] = (float)(acc[2] / cnt);
            // self-clean for next graph replay
            g_acc[0] = 0.0; g_acc[1] = 0.0; g_acc[2] = 0.0;
            g_done = 0u;
            __threadfence();
        }
    }
}

extern "C" void kernel_launch(void* const* d_in, const int* in_sizes, int n_in,
                              void* d_out, int out_size) {
    const float* yd = (const float*)d_in[0];
    const float* td = (const float*)d_in[1];
    const int T = in_sizes[0];

    int n_frames = T / HOP + 1;
    if (n_frames > MAX_FRAMES) n_frames = MAX_FRAMES;
    int n_cta = (n_frames + 3) / 4;

    fft_phase_kernel<<<n_cta, 256>>>(yd, td, T, n_frames);
    boundary_finalize_kernel<<<296, 256>>>((float*)d_out, n_frames, n_cta);
}

// round 5
// speedup vs baseline: 3.4458x; 1.0643x over previous
#include <cuda_runtime.h>
#include <math.h>

#define N_FFT 512
#define HOP 128
#define NBINS 257
#define MAX_FRAMES 32769
#define MAX_CTAS ((MAX_FRAMES + 3) / 4)
#define TWO_PI_F 6.28318530717958647692f

__device__ float g_first[(size_t)MAX_CTAS * NBINS];
__device__ float g_last[(size_t)MAX_CTAS * NBINS];
__device__ double g_acc[3];          // zero-init at load; self-cleaned each call
__device__ unsigned int g_done;      // ticket; self-cleaned

// ---------------- packed complex (f32x2) helpers ----------------
typedef unsigned long long cplx;     // lo = re, hi = im

__device__ __forceinline__ cplx cpack(float re, float im) {
    cplx r; asm("mov.b64 %0, {%1, %2};" : "=l"(r) : "f"(re), "f"(im)); return r;
}
__device__ __forceinline__ void cunpack(cplx a, float& re, float& im) {
    asm("mov.b64 {%0, %1}, %2;" : "=f"(re), "=f"(im) : "l"(a));
}
__device__ __forceinline__ cplx cswap(cplx a) {
    cplx r;
    asm("{\n\t.reg .f32 lo, hi;\n\tmov.b64 {lo, hi}, %1;\n\tmov.b64 %0, {hi, lo};\n\t}"
        : "=l"(r) : "l"(a));
    return r;
}
__device__ __forceinline__ cplx cadd2(cplx a, cplx b) {
    cplx r; asm("add.rn.f32x2 %0, %1, %2;" : "=l"(r) : "l"(a), "l"(b)); return r;
}
__device__ __forceinline__ cplx cmul2(cplx a, cplx b) {
    cplx r; asm("mul.rn.f32x2 %0, %1, %2;" : "=l"(r) : "l"(a), "l"(b)); return r;
}
__device__ __forceinline__ cplx cfma2(cplx a, cplx b, cplx c) {
    cplx r; asm("fma.rn.f32x2 %0, %1, %2, %3;" : "=l"(r) : "l"(a), "l"(b), "l"(c)); return r;
}
__device__ __forceinline__ float fneg(float x) {
    return __int_as_float(__float_as_int(x) ^ 0x80000000);
}

__device__ __forceinline__ int reflect_idx(int j, int T) {
    j = abs(j);
    if (j >= T) j = 2 * T - 2 - j;
    return j;
}

__device__ __forceinline__ float anti_wrap(float x) {
    return fabsf(fmaf(-rintf(x * (1.0f / TWO_PI_F)), TWO_PI_F, x));
}

// packed 8-point DFT, natural-order outputs.
__device__ __forceinline__ void dft8p(cplx x[8], cplx NEG1, cplx PMI, cplx CC) {
    cplx s0 = cadd2(x[0], x[4]);
    cplx s1 = cadd2(x[1], x[5]);
    cplx s2 = cadd2(x[2], x[6]);
    cplx s3 = cadd2(x[3], x[7]);
    cplx u0 = cfma2(x[4], NEG1, x[0]);
    cplx u1 = cfma2(x[5], NEG1, x[1]);
    cplx u2 = cfma2(x[6], NEG1, x[2]);
    cplx u3 = cfma2(x[7], NEG1, x[3]);

    cplx t1 = cmul2(CC, cfma2(cswap(u1), PMI, u1));
    cplx t2 = cmul2(cswap(u2), PMI);
    cplx t3 = cmul2(CC, cfma2(u3, NEG1, cmul2(cswap(u3), PMI)));

    cplx e0 = cadd2(s0, s2);
    cplx e2 = cfma2(s2, NEG1, s0);
    cplx e1 = cadd2(s1, s3);
    cplx d13 = cfma2(s3, NEG1, s1);
    cplx e3 = cmul2(cswap(d13), PMI);
    x[0] = cadd2(e0, e1);
    x[4] = cfma2(e1, NEG1, e0);
    x[2] = cadd2(e2, e3);
    x[6] = cfma2(e3, NEG1, e2);

    cplx o0 = cadd2(u0, t2);
    cplx o2 = cfma2(t2, NEG1, u0);
    cplx o1 = cadd2(t1, t3);
    cplx d13b = cfma2(t3, NEG1, t1);
    cplx o3 = cmul2(cswap(d13b), PMI);
    x[1] = cadd2(o0, o1);
    x[5] = cfma2(o1, NEG1, o0);
    x[3] = cadd2(o2, o3);
    x[7] = cfma2(o3, NEG1, o2);
}

__device__ __forceinline__ cplx ctw(cplx x, float wr, float wi) {
    cplx wrr = cpack(wr, wr);
    cplx wim = cpack(fneg(wi), wi);
    return cfma2(cswap(x), wim, cmul2(x, wrr));
}

// BIJECTIVE bank swizzle: XOR low 3 bits with the 8-block index (mod 8).
__device__ __forceinline__ int sw_addr(int f) {
    return f ^ ((f >> 3) & 7);
}

// 4 frames per 256-thread CTA; radix-8^3 packed-register FFT; fused loss sums.
__global__ __launch_bounds__(256) void fft_phase_kernel(
    const float* __restrict__ yd, const float* __restrict__ td,
    int T, int n_frames)
{
    __shared__ cplx sZ[4][576];
    __shared__ float dBuf[4][260];
    __shared__ float wsum[8][3];

    const int lt = threadIdx.x & 63;
    const int fl = threadIdx.x >> 6;
    const int frame = blockIdx.x * 4 + fl;
    const bool active = (frame < n_frames);

    const cplx NEG1 = cpack(-1.0f, -1.0f);
    const cplx PMI  = cpack(1.0f, -1.0f);
    const cplx CC   = cpack(0.70710678118654752440f, 0.70710678118654752440f);

    cplx x[8];

    if (active) {
        const int base = frame * HOP - (N_FFT / 2) + lt;
#pragma unroll
        for (int k = 0; k < 8; k++) {
            int j = reflect_idx(base + 64 * k, T);
            x[k] = cpack(yd[j], td[j]);
        }
    } else {
#pragma unroll
        for (int k = 0; k < 8; k++) x[k] = 0ull;
    }

    // ---- Stage A: dft8 over k, twiddle W512^{lt*v} ----
    dft8p(x, NEG1, PMI, CC);
    {
        float bs, bc;
        sincospif(-(float)lt * (1.0f / 256.0f), &bs, &bc);
        float wr = bc, wi = bs;
#pragma unroll
        for (int v = 1; v < 8; v++) {
            x[v] = ctw(x[v], wr, wi);
            float nr = wr * bc - wi * bs;
            float ni = wr * bs + wi * bc;
            wr = nr; wi = ni;
        }
    }
#pragma unroll
    for (int v = 0; v < 8; v++) sZ[fl][v * 72 + lt] = x[v];
    __syncthreads();

    // ---- Stage B: dft8 over t2, twiddle W64^{t1*m1} ----
    const int v2 = lt >> 3;
    const int t1 = lt & 7;
#pragma unroll
    for (int t2 = 0; t2 < 8; t2++) x[t2] = sZ[fl][v2 * 72 + t1 + 8 * t2];
    dft8p(x, NEG1, PMI, CC);
    {
        float bs, bc;
        sincospif(-(float)t1 * (1.0f / 32.0f), &bs, &bc);
        float wr = bc, wi = bs;
#pragma unroll
        for (int m1 = 1; m1 < 8; m1++) {
            x[m1] = ctw(x[m1], wr, wi);
            float nr = wr * bc - wi * bs;
            float ni = wr * bs + wi * bc;
            wr = nr; wi = ni;
        }
    }
    __syncthreads();
#pragma unroll
    for (int m1 = 0; m1 < 8; m1++) sZ[fl][(v2 * 8 + m1) * 9 + t1] = x[m1];
    __syncthreads();

    // ---- Stage C ----
    {
        const int rowbase = lt * 9;
#pragma unroll
        for (int k = 0; k < 8; k++) x[k] = sZ[fl][rowbase + k];
    }
    dft8p(x, NEG1, PMI, CC);
    __syncthreads();
    {
        const int fbase = ((lt & 7) << 3) | (lt >> 3);  // 8*m1 + v
#pragma unroll
        for (int m2 = 0; m2 < 8; m2++)
            sZ[fl][sw_addr(64 * m2 + fbase)] = x[m2];
    }
    __syncthreads();

    // ---- epilogue: split spectrum, d = angle(Y * conj(T)) ----
    if (active) {
        const size_t obase = (size_t)blockIdx.x * NBINS;
#pragma unroll
        for (int j = 0; j < 5; j++) {
            int f = lt + 64 * j;
            if (f <= 256) {
                float zkr, zki, znr, zni;
                cunpack(sZ[fl][sw_addr(f)], zkr, zki);
                int m = (N_FFT - f) & (N_FFT - 1);
                cunpack(sZ[fl][sw_addr(m)], znr, zni);
                float yre = zkr + znr;
                float yim = zki - zni;
                float tre = zki + zni;
                float tim = znr - zkr;
                float pre = yre * tre + yim * tim;
                float pim = yim * tre - yre * tim;
                float d = atan2f(pim, pre);
                dBuf[fl][f] = d;
                if (fl == 0) g_first[obase + f] = d;
                if (fl == 3) g_last[obase + f] = d;
            }
        }
    }
    __syncthreads();

    // ---- fused partial sums ----
    float s_ip = 0.0f, s_gd = 0.0f, s_iaf = 0.0f;
    const int tid = threadIdx.x;
#pragma unroll
    for (int fl2 = 0; fl2 < 4; fl2++) {
        int fr2 = blockIdx.x * 4 + fl2;
        if (fr2 >= n_frames) break;
        {
            float d0 = dBuf[fl2][tid];
            s_ip += anti_wrap(d0);
            float gdv = (tid == 0) ? d0 : (dBuf[fl2][tid - 1] - d0);
            s_gd += anti_wrap(gdv);
            if (fl2 > 0) s_iaf += anti_wrap(dBuf[fl2 - 1][tid] - d0);
        }
        if (tid == 0) {
            float d0 = dBuf[fl2][256];
            s_ip += anti_wrap(d0);
            s_gd += anti_wrap(dBuf[fl2][255] - d0);
            if (fl2 > 0) s_iaf += anti_wrap(dBuf[fl2 - 1][256] - d0);
        }
    }
#pragma unroll
    for (int o = 16; o > 0; o >>= 1) {
        s_ip  += __shfl_down_sync(0xFFFFFFFFu, s_ip,  o);
        s_gd  += __shfl_down_sync(0xFFFFFFFFu, s_gd,  o);
        s_iaf += __shfl_down_sync(0xFFFFFFFFu, s_iaf, o);
    }
    if ((tid & 31) == 0) {
        wsum[tid >> 5][0] = s_ip;
        wsum[tid >> 5][1] = s_gd;
        wsum[tid >> 5][2] = s_iaf;
    }
    __syncthreads();
    if (tid == 0) {
        double a0 = 0.0, a1 = 0.0, a2 = 0.0;
#pragma unroll
        for (int w = 0; w < 8; w++) {
            a0 += (double)wsum[w][0];
            a1 += (double)wsum[w][1];
            a2 += (double)wsum[w][2];
        }
        atomicAdd(&g_acc[0], a0);
        atomicAdd(&g_acc[1], a1);
        atomicAdd(&g_acc[2], a2);
    }
}

// Boundary iaf terms + finalize via ticket. Division-free: block <-> row.
__global__ __launch_bounds__(256) void boundary_finalize_kernel(
    float* __restrict__ out, int n_frames, int n_cta)
{
    __shared__ float wsum[8];
    float s_iaf = 0.0f;
    const int tid = threadIdx.x;

    for (int b = blockIdx.x; b < n_cta; b += gridDim.x) {
        const float* __restrict__ rowF = g_first + (size_t)b * NBINS;
        if (b == 0) {
            s_iaf += anti_wrap(rowF[tid]);
            if (tid == 0) s_iaf += anti_wrap(rowF[256]);
        } else {
            const float* __restrict__ rowL = g_last + (size_t)(b - 1) * NBINS;
            s_iaf += anti_wrap(rowL[tid] - rowF[tid]);
            if (tid == 0) s_iaf += anti_wrap(rowL[256] - rowF[256]);
        }
    }

#pragma unroll
    for (int o = 16; o > 0; o >>= 1)
        s_iaf += __shfl_down_sync(0xFFFFFFFFu, s_iaf, o);
    if ((tid & 31) == 0) wsum[tid >> 5] = s_iaf;
    __syncthreads();

    if (tid == 0) {
        double a = 0.0;
#pragma unroll
        for (int w = 0; w < 8; w++) a += (double)wsum[w];
        atomicAdd(&g_acc[2], a);
        __threadfence();
        unsigned int ticket = atomicAdd(&g_done, 1u);
        if (ticket == gridDim.x - 1) {
            double cnt = (double)n_frames * (double)NBINS;
            volatile double* acc = g_acc;
            out[0] = (float)(acc[0] / cnt);
            out[1] = (float)(acc[1] / cnt);
            out[2] = (float)(acc[2] / cnt);
            g_acc[0] = 0.0; g_acc[1] = 0.0; g_acc[2] = 0.0;
            g_done = 0u;
            __threadfence();
        }
    }
}

extern "C" void kernel_launch(void* const* d_in, const int* in_sizes, int n_in,
                              void* d_out, int out_size) {
    const float* yd = (const float*)d_in[0];
    const float* td = (const float*)d_in[1];
    const int T = in_sizes[0];

    int n_frames = T / HOP + 1;
    if (n_frames > MAX_FRAMES) n_frames = MAX_FRAMES;
    int n_cta = (n_frames + 3) / 4;

    fft_phase_kernel<<<n_cta, 256>>>(yd, td, T, n_frames);
    boundary_finalize_kernel<<<1184, 256>>>((float*)d_out, n_frames, n_cta);
}